// round 13
// baseline (speedup 1.0000x reference)
#include <cuda_runtime.h>
#include <math.h>
#include <stdint.h>

#define NF 5
#define D 64
#define NHID 128
#define H 8192     /* D*NHID */
#define BATCH 4096
#define BM 32
#define NTH 1024

#define XP   68    /* xs pitch */
#define W1P  68    /* w1 tile pitch per k-row */
#define W2P  136   /* w2 tile pitch per oc-row (staggered k-halves) */
#define TSP  132   /* ts/ps pitch */

typedef unsigned long long ull;

// Precomputed, batch-independent (plain layouts, zeros folded):
__device__ float g_wn1[NF * D * NHID * D];   // [f][i][k][j], zeros j>i
__device__ float g_wn2[NF * D * D * NHID];   // [f][i][oc][k], zeros oc<i
__device__ float g_c[NF * D * NHID];         // [f][i][k] wpl diag sum

__device__ __forceinline__ float fast_sp(float z) {
    return fmaxf(z, 0.f) + __logf(1.f + __expf(-fabsf(z)));
}
__device__ __forceinline__ void upk2(ull v, float& lo, float& hi) {
    asm("mov.b64 {%0,%1},%2;" : "=f"(lo), "=f"(hi) : "l"(v));
}
__device__ __forceinline__ ull ffma2(ull a, ull b, ull c) {
    ull d;
    asm("fma.rn.f32x2 %0,%1,%2,%3;" : "=l"(d) : "l"(a), "l"(b), "l"(c));
    return d;
}

// ---------------------------------------------------------------------------
__global__ void prep1(const float* __restrict__ W1, const float* __restrict__ d1) {
    int idx = blockIdx.x * blockDim.x + threadIdx.x;
    if (idx >= NF * H) return;
    int f = idx / H, r = idx % H;
    int i = r >> 7, k = r & 127;
    const float* Wrow = W1 + (size_t)(f * H + r) * D;
    float dv = d1[f * H + r];
    float wdiag = expf(Wrow[i]);
    float wsn = wdiag * wdiag;
    for (int j = 0; j < i; j++) { float wv = Wrow[j]; wsn += wv * wv; }
    float scale = expf(dv) * rsqrtf(wsn);
    float* dst = g_wn1 + ((size_t)(f * D + i) * NHID + k) * D;
    for (int j = 0; j < D; j++) {
        float wv = (j < i) ? Wrow[j] : ((j == i) ? wdiag : 0.f);
        dst[j] = wv * scale;
    }
    g_c[(f * D + i) * NHID + k] = dv + Wrow[i] - 0.5f * logf(wsn);
}

// ---------------------------------------------------------------------------
__global__ void prep2(const float* __restrict__ W2, const float* __restrict__ d2) {
    int f = blockIdx.x >> 6;
    int oc = blockIdx.x & 63;
    int tid = threadIdx.x;
    const float* Wrow = W2 + (size_t)(f * D + oc) * H;
    __shared__ float red[128];
    float wsn = 0.f;
    int lim = (oc + 1) * NHID;
    for (int j = tid; j < lim; j += 128) {
        int jb = j >> 7;
        float wv = (jb == oc) ? expf(Wrow[j]) : Wrow[j];
        wsn += wv * wv;
    }
    red[tid] = wsn;
    __syncthreads();
    for (int s = 64; s > 0; s >>= 1) {
        if (tid < s) red[tid] += red[tid + s];
        __syncthreads();
    }
    wsn = red[0];
    float dv = d2[f * D + oc];
    float scale = expf(dv) * rsqrtf(wsn);
    for (int j = tid; j < H; j += 128) {
        int jb = j >> 7, k = j & 127;
        float wv = (jb < oc) ? Wrow[j] : ((jb == oc) ? expf(Wrow[j]) : 0.f);
        g_wn2[((size_t)(f * D + jb) * D + oc) * NHID + k] = wv * scale;
    }
    g_c[(f * D + oc) * NHID + tid] += dv + Wrow[oc * NHID + tid] - 0.5f * logf(wsn);
}

// ---------------------------------------------------------------------------
__device__ __forceinline__ void stage_w1(int g, float* dst, int tid) {
    int inx = g & 63;
    int jl4 = (inx >> 2) + 1;
    const float* src = g_wn1 + (size_t)g * NHID * D;
    #pragma unroll
    for (int q = tid; q < NHID * 16; q += NTH) {
        int k = q >> 4, c4 = q & 15;
        if (c4 < jl4)
            *(float4*)(dst + k * W1P + c4 * 4) =
                *(const float4*)(src + k * D + c4 * 4);
    }
}
__device__ __forceinline__ void stage_w2(int g, float* dst, int tid) {
    int inx = g & 63;
    const float* src = g_wn2 + (size_t)g * D * NHID;
    #pragma unroll
    for (int q = tid; q < D * 32; q += NTH) {
        int o = q >> 5, c4 = q & 31;
        if ((o | 3) >= inx)
            *(float4*)(dst + o * W2P + c4 * 4 + ((c4 >= 16) ? 4 : 0)) =
                *(const float4*)(src + o * NHID + c4 * 4);
    }
}
__device__ __forceinline__ void stage_bc(int g, float* dst,
                                         const float* __restrict__ b1g, int tid) {
    if (tid < 64) {
        int inx = g & 63, fl = g >> 6;
        if (tid < 32)
            *(float4*)(dst + tid * 4) =
                *(const float4*)(b1g + (size_t)fl * H + inx * NHID + tid * 4);
        else
            *(float4*)(dst + tid * 4) =
                *(const float4*)(g_c + (size_t)g * NHID + (tid - 32) * 4);
    }
}

// phase1 (h for block i1, 2 rows/thread) + transcendental -> ts/ps targets
__device__ __forceinline__ void phase1_trans(
    int i1, const float* w1b, const float* bcb,
    float* tsn, float* psn, const float* xs, int kc, int rb)
{
    const float TWOLN2 = 1.3862943611198906f;
    ull a0[2] = {0ull, 0ull}, a1[2] = {0ull, 0ull};
    const float* wa = w1b + kc * W1P;
    const float* wb = w1b + (kc + 64) * W1P;
    #pragma unroll 4
    for (int j = 0; j <= i1; j += 4) {
        ulonglong2 wpa = *(const ulonglong2*)(wa + j);
        ulonglong2 wpb = *(const ulonglong2*)(wb + j);
        #pragma unroll
        for (int rr = 0; rr < 2; rr++) {
            ulonglong2 xp = *(const ulonglong2*)(xs + (rb + rr) * XP + j);
            a0[rr] = ffma2(xp.x, wpa.x, a0[rr]);
            a0[rr] = ffma2(xp.y, wpa.y, a0[rr]);
            a1[rr] = ffma2(xp.x, wpb.x, a1[rr]);
            a1[rr] = ffma2(xp.y, wpb.y, a1[rr]);
        }
    }
    float b1a = bcb[kc], b1b = bcb[kc + 64];
    float ca2 = bcb[128 + kc] + TWOLN2;
    float cb2 = bcb[128 + kc + 64] + TWOLN2;
    #pragma unroll
    for (int rr = 0; rr < 2; rr++) {
        int r = rb + rr;
        float l0, h0v, l1, h1v;
        upk2(a0[rr], l0, h0v);
        upk2(a1[rr], l1, h1v);
        float h0 = l0 + h0v + b1a;
        float h1 = l1 + h1v + b1b;
        float ah0 = fabsf(h0), ah1 = fabsf(h1);
        float E0 = __expf(-2.f * ah0);
        float E1 = __expf(-2.f * ah1);
        tsn[r * TSP + kc]      = copysignf(__fdividef(1.f - E0, 1.f + E0), h0);
        tsn[r * TSP + kc + 64] = copysignf(__fdividef(1.f - E1, 1.f + E1), h1);
        psn[r * TSP + kc]      = fmaf(-2.f, ah0 + __logf(1.f + E0), ca2);
        psn[r * TSP + kc + 64] = fmaf(-2.f, ah1 + __logf(1.f + E1), cb2);
    }
}

// ---------------------------------------------------------------------------
// Main fused kernel: 128 CTAs x 1024 threads (8 warps/SMSP). Software-
// pipelined slots, one barrier per slot. Phase2: warp = 4-oc quad x
// row-half; quads {s,7-s,8+s,15-s} per SMSP for exact balance.
// ---------------------------------------------------------------------------
__global__ void __launch_bounds__(NTH, 1) bnaf_main(
    const float* __restrict__ x, const float* __restrict__ b1g,
    const float* __restrict__ b2, const float* __restrict__ gates,
    float* __restrict__ out)
{
    extern __shared__ float sm[];
    float* xs  = sm;                          // BM*XP       = 2176
    float* w1t = xs + BM * XP;                // 2*128*W1P   = 17408
    float* w2t = w1t + 2 * NHID * W1P;        // 2*64*W2P    = 17408
    float* bc  = w2t + 2 * D * W2P;           // 512
    float* tsb = bc + 512;                    // 2*BM*TSP    = 8448
    float* psb = tsb + 2 * BM * TSP;          // 2*BM*TSP    = 8448
    float* lds_s = psb + 2 * BM * TSP;        // BM

    const int tid = threadIdx.x;
    const int b0 = blockIdx.x * BM;

    // phase1 mapping: kc column pair, 2 rows
    const int kc = tid & 63;
    const int rb = (tid >> 6) * 2;
    // phase2 mapping: 32 warps -> 16 quads x 2 row-halves, SMSP-balanced
    const int wid = tid >> 5, lane = tid & 31;
    const int q4 = wid & 3;              // SMSP
    const int u_ = (wid >> 2) & 3;
    const int qd = (u_ == 0) ? q4 : (u_ == 1) ? (7 - q4)
                 : (u_ == 2) ? (8 + q4) : (15 - q4);
    const int rh = wid >> 4;
    const int row2 = rh * 16 + (lane >> 1);
    const int kh = lane & 1;
    const int oc0 = qd * 4;

    {   // load x tile
        for (int q = tid; q < BM * 16; q += NTH) {
            int r = q >> 4, c4 = q & 15;
            *(float4*)(xs + r * XP + c4 * 4) =
                *(const float4*)(x + (size_t)(b0 + r) * D + c4 * 4);
        }
    }
    if (tid < BM) lds_s[tid] = 0.f;

    for (int f = 0; f < NF; f++) {
        const int base = f * D;
        const bool gated = (f < NF - 1);
        const float gate = gated ? gates[f] : 0.f;
        const float sg = gated ? (1.f / (1.f + __expf(-gate))) : 0.f;
        const float spg = gated ? fast_sp(gate) : 0.f;

        ull yp[4] = {0ull, 0ull, 0ull, 0ull};

        // ---- prologue: stage w1(0),w1(1),w2(0),bc(0),bc(1); then phase1(0)
        stage_w1(base + 0, w1t, tid);
        stage_w1(base + 1, w1t + NHID * W1P, tid);
        stage_w2(base + 0, w2t, tid);
        stage_bc(base + 0, bc, b1g, tid);
        stage_bc(base + 1, bc + 256, b1g, tid);
        __syncthreads();
        phase1_trans(0, w1t, bc, tsb, psb, xs, kc, rb);
        __syncthreads();

        for (int ii = 0; ii < D; ii++) {
            const int cur = ii & 1, nxt = cur ^ 1;

            // stage ahead (LDGs issue early; buffers free by parity)
            if (ii < D - 2) {
                stage_w1(base + ii + 2, w1t + cur * (NHID * W1P), tid);
                stage_bc(base + ii + 2, bc + cur * 256, b1g, tid);
            }
            if (ii < D - 1)
                stage_w2(base + ii + 1, w2t + nxt * (D * W2P), tid);

            // phase1(ii+1) -> ts/ps[nxt]
            if (ii < D - 1)
                phase1_trans(ii + 1, w1t + nxt * (NHID * W1P), bc + nxt * 256,
                             tsb + nxt * (BM * TSP), psb + nxt * (BM * TSP),
                             xs, kc, rb);

            // phase2(ii): reads ts[cur], w2[cur]; exact quad skip
            if (oc0 + 3 >= ii) {
                const float* tr = tsb + cur * (BM * TSP) + row2 * TSP + kh * 64;
                const float* uq = w2t + cur * (D * W2P) + oc0 * W2P + kh * 68;
                #pragma unroll 4
                for (int k = 0; k < 64; k += 4) {
                    ulonglong2 tp = *(const ulonglong2*)(tr + k);
                    #pragma unroll
                    for (int m = 0; m < 4; m++) {
                        ulonglong2 q = *(const ulonglong2*)(uq + m * W2P + k);
                        yp[m] = ffma2(tp.x, q.x, yp[m]);
                        yp[m] = ffma2(tp.y, q.y, yp[m]);
                    }
                }
            }

            // lse(ii): one warp per row, one LDS.128 per lane
            {
                const float* pr = psb + cur * (BM * TSP) + wid * TSP + lane * 4;
                float4 v = *(const float4*)pr;
                float mx = fmaxf(fmaxf(v.x, v.y), fmaxf(v.z, v.w));
                #pragma unroll
                for (int o2 = 16; o2 > 0; o2 >>= 1)
                    mx = fmaxf(mx, __shfl_xor_sync(0xffffffffu, mx, o2));
                float se = __expf(v.x - mx) + __expf(v.y - mx)
                         + __expf(v.z - mx) + __expf(v.w - mx);
                #pragma unroll
                for (int o2 = 16; o2 > 0; o2 >>= 1)
                    se += __shfl_xor_sync(0xffffffffu, se, o2);
                if (lane == 0) {
                    float gg = mx + __logf(se);
                    lds_s[wid] += gated ? (fast_sp(gg + gate) - spg) : gg;
                }
            }
            __syncthreads();
        }

        // ---- combine k-half partials, gate/reverse or final output
        float ysum[4];
        #pragma unroll
        for (int m = 0; m < 4; m++) {
            float lo, hi;
            upk2(yp[m], lo, hi);
            float p = lo + hi;
            p += __shfl_xor_sync(0xffffffffu, p, 1);
            ysum[m] = p + b2[f * D + oc0 + m];
        }
        if (gated) {
            float xo[4];
            #pragma unroll
            for (int m = 0; m < 4; m++)
                xo[m] = sg * ysum[m] + (1.f - sg) * xs[row2 * XP + oc0 + m];
            __syncthreads();
            if (kh == 0) {
                #pragma unroll
                for (int m = 0; m < 4; m++)
                    xs[row2 * XP + 63 - (oc0 + m)] = xo[m];
            }
            __syncthreads();
        } else {
            if (kh == 0) {
                #pragma unroll
                for (int m = 0; m < 4; m++)
                    out[(size_t)(b0 + row2) * D + oc0 + m] = ysum[m];
            }
        }
    }

    if (tid < BM) out[(size_t)BATCH * D + b0 + tid] = lds_s[tid];
}

static const int SMEM_BYTES =
    (BM * XP + 2 * NHID * W1P + 2 * D * W2P + 512 + 4 * BM * TSP + BM) * 4;

extern "C" void kernel_launch(void* const* d_in, const int* in_sizes, int n_in,
                              void* d_out, int out_size) {
    const float* x  = (const float*)d_in[0];
    const float* W1 = (const float*)d_in[1];
    const float* d1 = (const float*)d_in[2];
    const float* b1 = (const float*)d_in[3];
    const float* W2 = (const float*)d_in[4];
    const float* d2 = (const float*)d_in[5];
    const float* b2 = (const float*)d_in[6];
    const float* gates = (const float*)d_in[7];
    float* out = (float*)d_out;

    prep1<<<(NF * H + 255) / 256, 256>>>(W1, d1);
    prep2<<<NF * D, 128>>>(W2, d2);

    cudaFuncSetAttribute(bnaf_main, cudaFuncAttributeMaxDynamicSharedMemorySize, SMEM_BYTES);
    bnaf_main<<<BATCH / BM, NTH, SMEM_BYTES>>>(x, b1, b2, gates, out);
}